// round 13
// baseline (speedup 1.0000x reference)
#include <cuda_runtime.h>
#include <cuda_bf16.h>
#include <cstdint>
#include <math.h>

#define BB 2
#define TT 2048
#define CC 2048
#define NH 32
#define NG 8
#define HD 64

// ---------------- scratch (no allocations allowed) ----------------
__device__ float g_QP[BB * TT * CC];
__device__ float g_VP[BB * TT * NG * HD];
__device__ float g_qc[BB * TT * CC];
__device__ float g_kc[BB * TT * CC];
__device__ float g_vc[BB * TT * CC];
__device__ float g_wq[CC * CC];
__device__ float g_wk[NG * HD * CC];
__device__ float g_wv[NG * HD * CC];
__device__ float g_wp[CC * CC];
__device__ float g_Kp[BB * NG * TT * HD];    // tf32-rounded fp32 K, [bg][t][hd]
__device__ float g_Vt[BB * NG * HD * TT];    // tf32-rounded fp32 V transposed, [bg][hd][t]
__device__ float g_O[BB * TT * CC];

// ---------------- helpers ----------------
__device__ __forceinline__ uint32_t f2tf32(float x) {
    uint32_t r;
    asm("cvt.rna.tf32.f32 %0, %1;" : "=r"(r) : "f"(x));
    return r;
}
__device__ __forceinline__ float fast_ex2(float x) {
    float r;
    asm("ex2.approx.f32 %0, %1;" : "=f"(r) : "f"(x));
    return r;
}
__device__ __forceinline__ void mma_tf32(float& d0, float& d1, float& d2, float& d3,
                                         uint32_t a0, uint32_t a1, uint32_t a2, uint32_t a3,
                                         uint32_t b0, uint32_t b1)
{
    asm volatile(
        "mma.sync.aligned.m16n8k8.row.col.f32.tf32.tf32.f32 "
        "{%0,%1,%2,%3}, {%4,%5,%6,%7}, {%8,%9}, {%0,%1,%2,%3};"
        : "+f"(d0), "+f"(d1), "+f"(d2), "+f"(d3)
        : "r"(a0), "r"(a1), "r"(a2), "r"(a3), "r"(b0), "r"(b1));
}
__device__ __forceinline__ uint32_t smem_u32(const void* p) {
    uint32_t a;
    asm("{ .reg .u64 t; cvta.to.shared.u64 t, %1; cvt.u32.u64 %0, t; }" : "=r"(a) : "l"(p));
    return a;
}
__device__ __forceinline__ void cp16(uint32_t dst, const void* src) {
    asm volatile("cp.async.ca.shared.global [%0], [%1], 16;" :: "r"(dst), "l"(src));
}
__device__ __forceinline__ void cp_commit() { asm volatile("cp.async.commit_group;" ::: "memory"); }
template<int N> __device__ __forceinline__ void cp_wait() {
    asm volatile("cp.async.wait_group %0;" :: "n"(N) : "memory");
}

// ---------------- fused tf32 conversion: 7 tensors, one launch ----------------
#define NBIG4 (BB * TT * CC / 4)
#define NWQ4  (CC * CC / 4)
#define NWK4  (NG * HD * CC / 4)

__global__ void __launch_bounds__(256) conv_all(
    const float* __restrict__ q, const float* __restrict__ k, const float* __restrict__ v,
    const float* __restrict__ Wq, const float* __restrict__ Wk,
    const float* __restrict__ Wv, const float* __restrict__ Wp,
    float* __restrict__ qc, float* __restrict__ kc, float* __restrict__ vc,
    float* __restrict__ wq, float* __restrict__ wk, float* __restrict__ wv,
    float* __restrict__ wp)
{
    const float* s; float* d; int n4;
    switch (blockIdx.y) {
        case 0: s = q;  d = qc; n4 = NBIG4; break;
        case 1: s = k;  d = kc; n4 = NBIG4; break;
        case 2: s = v;  d = vc; n4 = NBIG4; break;
        case 3: s = Wq; d = wq; n4 = NWQ4;  break;
        case 4: s = Wp; d = wp; n4 = NWQ4;  break;
        case 5: s = Wk; d = wk; n4 = NWK4;  break;
        default: s = Wv; d = wv; n4 = NWK4; break;
    }
    int i = blockIdx.x * 256 + threadIdx.x;
    if (i >= n4) return;
    float4 t = ((const float4*)s)[i];
    t.x = __uint_as_float(f2tf32(t.x));
    t.y = __uint_as_float(f2tf32(t.y));
    t.z = __uint_as_float(f2tf32(t.z));
    t.w = __uint_as_float(f2tf32(t.w));
    ((float4*)d)[i] = t;
}

// ---------------- V pack+transpose (tf32-rounded fp32, [bg][hd][t]) ----------------
__global__ void __launch_bounds__(256) pack_v(const float* __restrict__ VP,
                                              float* __restrict__ Vt)
{
    __shared__ float tile[64][65];
    const int bg = blockIdx.y;
    const int b  = bg >> 3, g = bg & 7;
    const int t0 = blockIdx.x * 64;
    const int tid = threadIdx.x;

#pragma unroll
    for (int it = 0; it < 4; it++) {
        int idx = tid + it * 256;
        int tl = idx >> 4, c4 = idx & 15;
        float4 v = *(const float4*)(VP + ((size_t)b * TT + t0 + tl) * (NG * HD) + g * 64 + c4 * 4);
        tile[tl][c4 * 4 + 0] = v.x; tile[tl][c4 * 4 + 1] = v.y;
        tile[tl][c4 * 4 + 2] = v.z; tile[tl][c4 * 4 + 3] = v.w;
    }
    __syncthreads();
#pragma unroll
    for (int it = 0; it < 4; it++) {
        int idx = tid + it * 256;       // float4 id over 64x64
        int hd = idx >> 4, t4 = (idx & 15) * 4;
        float4 o;
        o.x = __uint_as_float(f2tf32(tile[t4 + 0][hd]));
        o.y = __uint_as_float(f2tf32(tile[t4 + 1][hd]));
        o.z = __uint_as_float(f2tf32(tile[t4 + 2][hd]));
        o.w = __uint_as_float(f2tf32(tile[t4 + 3][hd]));
        *(float4*)(Vt + ((size_t)bg * 64 + hd) * TT + t0 + t4) = o;
    }
}

// ====== tf32 GEMM: 128x128 CTA, 64x32 warp tile, BK=32, 3-stage SINGLE-SYNC ring, 2 CTAs/SM ======
#define GST 36
#define STGF (256 * GST)                      // 9216 floats = 36864 B / stage
#define NSTG 3
#define GEMM_SMEM_BYTES (NSTG * STGF * 4)     // 110592

__device__ __forceinline__ void gemm_body(
    const float* __restrict__ A, const float* __restrict__ Bm,
    const float* __restrict__ bias, float* __restrict__ Cm,
    int N, int K, int bm, int bn,
    float* __restrict__ Kp)                   // non-null -> tf32-rounded packed-K epilogue
{
    extern __shared__ float smem[];
    const uint32_t smb = smem_u32(smem);

    const int tid  = threadIdx.x;
    const int wid  = tid >> 5;
    const int lane = tid & 31;
    const int grp  = lane >> 2;
    const int tig  = lane & 3;
    const int warp_m = wid >> 2;   // 0..1
    const int warp_n = wid & 3;    // 0..3

    float acc[4][4][4];
#pragma unroll
    for (int i = 0; i < 4; i++)
#pragma unroll
        for (int j = 0; j < 4; j++)
#pragma unroll
            for (int r = 0; r < 4; r++) acc[i][j][r] = 0.f;

    const int NS = K / 32;

#define GISSUE(sl, it) do {                                                             \
        const int _k0 = (it) * 32;                                                      \
        const uint32_t _sb = smb + (uint32_t)(sl) * (STGF * 4);                         \
        _Pragma("unroll")                                                               \
        for (int _j = 0; _j < 4; _j++) {                                                \
            int _sl2 = tid + _j * 256;                                                  \
            int _r = _sl2 >> 3, _c4 = (_sl2 & 7) * 4;                                   \
            cp16(_sb + (uint32_t)(_r * GST + _c4) * 4,                                  \
                 A + (size_t)(bm + _r) * K + _k0 + _c4);                                \
            cp16(_sb + (uint32_t)((128 + _r) * GST + _c4) * 4,                          \
                 Bm + (size_t)(bn + _r) * K + _k0 + _c4);                               \
        }                                                                               \
    } while (0)

    GISSUE(0, 0); cp_commit();
    GISSUE(1, 1); cp_commit();

    for (int it = 0; it < NS; it++) {
        cp_wait<1>();
        __syncthreads();                       // single sync per stage
        const int nxt = it + 2;
        if (nxt < NS) { GISSUE(nxt % NSTG, nxt); }   // slot consumed at it-1, safe past sync
        cp_commit();

        const float* Sb  = smem + (it % NSTG) * STGF;
        const float* Bsb = Sb + 128 * GST;
#pragma unroll
        for (int kk = 0; kk < 32; kk += 8) {
            uint2 bfr[4];
#pragma unroll
            for (int na = 0; na < 4; na++)
                bfr[na] = *(const uint2*)(Bsb + (warp_n * 32 + na * 8 + grp) * GST + kk + 2 * tig);
#pragma unroll
            for (int ma = 0; ma < 4; ma++) {
                uint2 av0 = *(const uint2*)(Sb + (warp_m * 64 + ma * 16 + grp) * GST + kk + 2 * tig);
                uint2 av1 = *(const uint2*)(Sb + (warp_m * 64 + ma * 16 + 8 + grp) * GST + kk + 2 * tig);
#pragma unroll
                for (int na = 0; na < 4; na++) {
                    mma_tf32(acc[ma][na][0], acc[ma][na][1], acc[ma][na][2], acc[ma][na][3],
                             av0.x, av1.x, av0.y, av1.y, bfr[na].x, bfr[na].y);
                }
            }
        }
    }
#undef GISSUE

    if (Kp) {
        // packed-K epilogue: tf32-rounded fp32, layout [bg][t][hd]
#pragma unroll
        for (int na = 0; na < 4; na++) {
            const int col = bn + warp_n * 32 + na * 8 + 2 * tig;   // 0..511
            const int g   = col >> 6;
            const int hd  = col & 63;
#pragma unroll
            for (int ma = 0; ma < 4; ma++) {
                const int row = bm + warp_m * 64 + ma * 16 + grp;
                const int b = row >> 11, t = row & (TT - 1);
                float* o = Kp + ((size_t)(b * NG + g) * TT + t) * HD + hd;
                *(float2*)o = make_float2(__uint_as_float(f2tf32(acc[ma][na][0])),
                                          __uint_as_float(f2tf32(acc[ma][na][1])));
                *(float2*)(o + 8 * HD) = make_float2(__uint_as_float(f2tf32(acc[ma][na][2])),
                                                     __uint_as_float(f2tf32(acc[ma][na][3])));
            }
        }
    } else {
#pragma unroll
        for (int na = 0; na < 4; na++) {
            const int col = bn + warp_n * 32 + na * 8 + 2 * tig;
            float b0 = 0.f, b1 = 0.f;
            if (bias) { b0 = bias[col]; b1 = bias[col + 1]; }
#pragma unroll
            for (int ma = 0; ma < 4; ma++) {
                const int row = bm + warp_m * 64 + ma * 16 + grp;
                float2 v0 = make_float2(acc[ma][na][0] + b0, acc[ma][na][1] + b1);
                float2 v1 = make_float2(acc[ma][na][2] + b0, acc[ma][na][3] + b1);
                *(float2*)(Cm + (size_t)row * N + col) = v0;
                *(float2*)(Cm + (size_t)(row + 8) * N + col) = v1;
            }
        }
    }
}

__global__ void __launch_bounds__(256, 2) gemm_tc(
    const float* __restrict__ A, const float* __restrict__ Bm,
    const float* __restrict__ bias, float* __restrict__ Cm, int N, int K)
{
    gemm_body(A, Bm, bias, Cm, N, K, blockIdx.y * 128, blockIdx.x * 128, nullptr);
}

__global__ void __launch_bounds__(256, 2) gemm_kv(
    const float* __restrict__ kc, const float* __restrict__ vc,
    const float* __restrict__ wk, const float* __restrict__ wv,
    float* __restrict__ Kp, float* __restrict__ VP)
{
    const bool isV = blockIdx.x >= 4;
    if (isV)
        gemm_body(vc, wv, nullptr, VP, NG * HD, CC, blockIdx.y * 128, (blockIdx.x & 3) * 128,
                  nullptr);
    else
        gemm_body(kc, wk, nullptr, nullptr, NG * HD, CC, blockIdx.y * 128, (blockIdx.x & 3) * 128,
                  Kp);
}

// ============== flash attention: all-tf32 MMA (S + PV), cp.async ring ==============
// stage layout (words): K fp32 [64 x 72] at 0, Vt fp32 [64 hd x 72] at 4608
#define KST 72
#define STW 9216
#define ATTN_SMEM_BYTES (2 * STW * 4)   // 73728
#define QSCALE 0.1803365407f            // 0.125 * log2(e)

__global__ void __launch_bounds__(256, 1) attn_mma(
    const float* __restrict__ QP, const float* __restrict__ Kp,
    const float* __restrict__ Vtg, float* __restrict__ O)
{
    extern __shared__ uint32_t sm[];
    const uint32_t smb = smem_u32(sm);

    const int bh = blockIdx.y;
    const int b  = bh >> 5;
    const int h  = bh & 31;
    const int g  = h & 7;
    const int bg = b * NG + g;
    const int q0 = blockIdx.x * 128;

    const float* Qg = QP + ((size_t)b * TT + q0) * CC + h * HD;
    const float* Kg = Kp + (size_t)bg * TT * HD;
    const float* Vg = Vtg + (size_t)bg * 64 * TT;

    const int tid  = threadIdx.x;
    const int wid  = tid >> 5;
    const int lane = tid & 31;
    const int grp  = lane >> 2;
    const int tig  = lane & 3;
    const int m0   = wid * 16;

#define ATTN_ISSUE(s, kv) do {                                                            \
        _Pragma("unroll")                                                                 \
        for (int _it = 0; _it < 4; _it++) {                                               \
            int _ch = tid + _it * 256;                                                    \
            int _r = _ch >> 4, _c4 = (_ch & 15) * 4;                                      \
            cp16(smb + (uint32_t)((s) * STW + _r * KST + _c4) * 4,                        \
                 Kg + (size_t)((kv) + _r) * HD + _c4);                                    \
        }                                                                                 \
        _Pragma("unroll")                                                                 \
        for (int _it = 0; _it < 4; _it++) {                                               \
            int _ch = tid + _it * 256;                                                    \
            int _hd = _ch >> 4, _c4 = (_ch & 15) * 4;                                     \
            cp16(smb + (uint32_t)((s) * STW + 4608 + _hd * KST + _c4) * 4,                \
                 Vg + (size_t)_hd * TT + (kv) + _c4);                                     \
        }                                                                                 \
    } while (0)

    ATTN_ISSUE(0, 0);  cp_commit();
    ATTN_ISSUE(1, 64); cp_commit();

    // Q tf32 fragments straight from gmem (k-permuted: slots (tig,tig+4) <- hd (2tig,2tig+1))
    uint32_t qa[8][4];
#pragma unroll
    for (int c = 0; c < 8; c++) {
#pragma unroll
        for (int rr = 0; rr < 2; rr++) {
            const int row = m0 + grp + rr * 8;
            float2 v = *(const float2*)(Qg + (size_t)row * CC + 8 * c + 2 * tig);
            qa[c][rr]     = f2tf32(v.x * QSCALE);
            qa[c][rr + 2] = f2tf32(v.y * QSCALE);
        }
    }

    float oacc[8][4];
#pragma unroll
    for (int i = 0; i < 8; i++)
#pragma unroll
        for (int j = 0; j < 4; j++) oacc[i][j] = 0.f;
    float m_r0 = -INFINITY, m_r1 = -INFINITY, l_r0 = 0.f, l_r1 = 0.f;

    for (int tile = 0; tile < TT / 64; tile++) {
        cp_wait<1>();
        __syncthreads();
        const int s = tile & 1;
        const uint32_t* Ks = sm + s * STW;
        const uint32_t* Vs = Ks + 4608;

        // ---- S = Q @ K^T  (tf32, 8 hd-chunks x 8 key-atoms) ----
        float sacc[8][4];
#pragma unroll
        for (int i = 0; i < 8; i++)
#pragma unroll
            for (int j = 0; j < 4; j++) sacc[i][j] = 0.f;
#pragma unroll
        for (int c = 0; c < 8; c++) {
#pragma unroll
            for (int gg = 0; gg < 8; gg++) {
                uint2 kf = *(const uint2*)(Ks + (8 * gg + grp) * KST + 8 * c + 2 * tig);
                mma_tf32(sacc[gg][0], sacc[gg][1], sacc[gg][2], sacc[gg][3],
                         qa[c][0], qa[c][1], qa[c][2], qa[c][3], kf.x, kf.y);
            }
        }

        // ---- online softmax (base 2) ----
        float rm0 = -INFINITY, rm1 = -INFINITY;
#pragma unroll
        for (int gg = 0; gg < 8; gg++) {
            rm0 = fmaxf(rm0, fmaxf(sacc[gg][0], sacc[gg][1]));
            rm1 = fmaxf(rm1, fmaxf(sacc[gg][2], sacc[gg][3]));
        }
        rm0 = fmaxf(rm0, __shfl_xor_sync(0xffffffffu, rm0, 1));
        rm0 = fmaxf(rm0, __shfl_xor_sync(0xffffffffu, rm0, 2));
        rm1 = fmaxf(rm1, __shfl_xor_sync(0xffffffffu, rm1, 1));
        rm1 = fmaxf(rm1, __shfl_xor_sync(0xffffffffu, rm1, 2));

        float nm0 = fmaxf(m_r0, rm0), nm1 = fmaxf(m_r1, rm1);
        float sc0 = fast_ex2(m_r0 - nm0), sc1 = fast_ex2(m_r1 - nm1);
        m_r0 = nm0; m_r1 = nm1;

        float rs0 = 0.f, rs1 = 0.f;
#pragma unroll
        for (int gg = 0; gg < 8; gg++) {
            sacc[gg][0] = fast_ex2(sacc[gg][0] - nm0);
            sacc[gg][1] = fast_ex2(sacc[gg][1] - nm0);
            sacc[gg][2] = fast_ex2(sacc[gg][2] - nm1);
            sacc[gg][3] = fast_ex2(sacc[gg][3] - nm1);
            rs0 += sacc[gg][0] + sacc[gg][1];
            rs1 += sacc[gg][2] + sacc[gg][3];
        }
        rs0 += __shfl_xor_sync(0xffffffffu, rs0, 1);
        rs0 += __shfl_xor_sync(0xffffffffu, rs0, 2);
        rs1 += __shfl_xor_sync(0xffffffffu, rs1, 1);
        rs1 += __shfl_xor_sync(0xffffffffu, rs1, 2);
        l_r0 = l_r0 * sc0 + rs0;
        l_r1 = l_r1 * sc1 + rs1;
#pragma unroll
        for (int i = 0; i < 8; i++) {
            oacc[i][0] *= sc0; oacc[i][1] *= sc0;
            oacc[i][2] *= sc1; oacc[i][3] *= sc1;
        }

        // ---- O += P @ V  (tf32, permuted k: slots (tig,tig+4) <- keys (8c+2tig, 8c+2tig+1)) ----
#pragma unroll
        for (int c = 0; c < 8; c++) {
            const uint32_t pa0 = f2tf32(sacc[c][0]);
            const uint32_t pa1 = f2tf32(sacc[c][2]);
            const uint32_t pa2 = f2tf32(sacc[c][1]);
            const uint32_t pa3 = f2tf32(sacc[c][3]);
#pragma unroll
            for (int hh = 0; hh < 8; hh++) {
                uint2 vf = *(const uint2*)(Vs + (8 * hh + grp) * KST + 8 * c + 2 * tig);
                mma_tf32(oacc[hh][0], oacc[hh][1], oacc[hh][2], oacc[hh][3],
                         pa0, pa1, pa2, pa3, vf.x, vf.y);
            }
        }

        __syncthreads();
        if (tile + 2 < TT / 64) { ATTN_ISSUE(s, (tile + 2) * 64); }
        cp_commit();
    }
#undef ATTN_ISSUE

    const float inv0 = 1.0f / l_r0, inv1 = 1.0f / l_r1;
    float* Og = O + ((size_t)b * TT + q0) * CC + h * HD;
    const int r0 = m0 + grp, r1 = m0 + grp + 8;
#pragma unroll
    for (int hh = 0; hh < 8; hh++) {
        const int col = 8 * hh + 2 * tig;
        float2 v0 = make_float2(__uint_as_float(f2tf32(oacc[hh][0] * inv0)),
                                __uint_as_float(f2tf32(oacc[hh][1] * inv0)));
        float2 v1 = make_float2(__uint_as_float(f2tf32(oacc[hh][2] * inv1)),
                                __uint_as_float(f2tf32(oacc[hh][3] * inv1)));
        *(float2*)(Og + (size_t)r0 * CC + col) = v0;
        *(float2*)(Og + (size_t)r1 * CC + col) = v1;
    }
}

// ---------------- launch ----------------
extern "C" void kernel_launch(void* const* d_in, const int* in_sizes, int n_in,
                              void* d_out, int out_size)
{
    const float* q  = (const float*)d_in[0];
    const float* k  = (const float*)d_in[1];
    const float* v  = (const float*)d_in[2];
    const float* Wq = (const float*)d_in[3];
    const float* Wk = (const float*)d_in[4];
    const float* Wv = (const float*)d_in[5];
    const float* Wp = (const float*)d_in[6];
    const float* bp = (const float*)d_in[7];
    float* out = (float*)d_out;

    float *pQP, *pVP, *pO, *pqc, *pkc, *pvc, *pwq, *pwk, *pwv, *pwp, *pKp, *pVt;
    cudaGetSymbolAddress((void**)&pQP, g_QP);
    cudaGetSymbolAddress((void**)&pVP, g_VP);
    cudaGetSymbolAddress((void**)&pO,  g_O);
    cudaGetSymbolAddress((void**)&pqc, g_qc);
    cudaGetSymbolAddress((void**)&pkc, g_kc);
    cudaGetSymbolAddress((void**)&pvc, g_vc);
    cudaGetSymbolAddress((void**)&pwq, g_wq);
    cudaGetSymbolAddress((void**)&pwk, g_wk);
    cudaGetSymbolAddress((void**)&pwv, g_wv);
    cudaGetSymbolAddress((void**)&pwp, g_wp);
    cudaGetSymbolAddress((void**)&pKp, g_Kp);
    cudaGetSymbolAddress((void**)&pVt, g_Vt);

    cudaFuncSetAttribute(gemm_tc,  cudaFuncAttributeMaxDynamicSharedMemorySize, GEMM_SMEM_BYTES);
    cudaFuncSetAttribute(gemm_kv,  cudaFuncAttributeMaxDynamicSharedMemorySize, GEMM_SMEM_BYTES);
    cudaFuncSetAttribute(attn_mma, cudaFuncAttributeMaxDynamicSharedMemorySize, ATTN_SMEM_BYTES);

    const int M = BB * TT;  // 4096

    conv_all<<<dim3(NBIG4 / 256, 7), 256>>>(q, k, v, Wq, Wk, Wv, Wp,
                                            pqc, pkc, pvc, pwq, pwk, pwv, pwp);

    gemm_tc<<<dim3(CC / 128, M / 128), 256, GEMM_SMEM_BYTES>>>(pqc, pwq, nullptr, pQP, CC, CC);
    gemm_kv<<<dim3(8, M / 128), 256, GEMM_SMEM_BYTES>>>(pkc, pvc, pwk, pwv, pKp, pVP);
    pack_v<<<dim3(TT / 64, BB * NG), 256>>>(pVP, pVt);

    attn_mma<<<dim3(TT / 128, BB * NH), 256, ATTN_SMEM_BYTES>>>(pQP, pKp, pVt, pO);

    gemm_tc<<<dim3(CC / 128, M / 128), 256, GEMM_SMEM_BYTES>>>(pO, pwp, bp, out, CC, CC);
}

// round 14
// speedup vs baseline: 1.0946x; 1.0946x over previous
#include <cuda_runtime.h>
#include <cuda_bf16.h>
#include <cstdint>
#include <math.h>

#define BB 2
#define TT 2048
#define CC 2048
#define NH 32
#define NG 8
#define HD 64

// ---------------- scratch (no allocations allowed) ----------------
__device__ float g_QP[BB * TT * CC];
__device__ float g_VP[BB * TT * NG * HD];
__device__ float g_qc[BB * TT * CC];
__device__ float g_kc[BB * TT * CC];
__device__ float g_vc[BB * TT * CC];
__device__ float g_wq[CC * CC];
__device__ float g_wk[NG * HD * CC];
__device__ float g_wv[NG * HD * CC];
__device__ float g_wp[CC * CC];
__device__ float g_Kp[BB * NG * TT * HD];    // tf32-rounded fp32 K, [bg][t][hd]
__device__ float g_Vt[BB * NG * HD * TT];    // tf32-rounded fp32 V transposed, [bg][hd][t]
__device__ float g_O[BB * TT * CC];

// ---------------- helpers ----------------
__device__ __forceinline__ uint32_t f2tf32(float x) {
    uint32_t r;
    asm("cvt.rna.tf32.f32 %0, %1;" : "=r"(r) : "f"(x));
    return r;
}
__device__ __forceinline__ float fast_ex2(float x) {
    float r;
    asm("ex2.approx.f32 %0, %1;" : "=f"(r) : "f"(x));
    return r;
}
__device__ __forceinline__ void mma_tf32(float& d0, float& d1, float& d2, float& d3,
                                         uint32_t a0, uint32_t a1, uint32_t a2, uint32_t a3,
                                         uint32_t b0, uint32_t b1)
{
    asm volatile(
        "mma.sync.aligned.m16n8k8.row.col.f32.tf32.tf32.f32 "
        "{%0,%1,%2,%3}, {%4,%5,%6,%7}, {%8,%9}, {%0,%1,%2,%3};"
        : "+f"(d0), "+f"(d1), "+f"(d2), "+f"(d3)
        : "r"(a0), "r"(a1), "r"(a2), "r"(a3), "r"(b0), "r"(b1));
}
__device__ __forceinline__ uint32_t smem_u32(const void* p) {
    uint32_t a;
    asm("{ .reg .u64 t; cvta.to.shared.u64 t, %1; cvt.u32.u64 %0, t; }" : "=r"(a) : "l"(p));
    return a;
}
__device__ __forceinline__ void cp16(uint32_t dst, const void* src) {
    asm volatile("cp.async.ca.shared.global [%0], [%1], 16;" :: "r"(dst), "l"(src));
}
__device__ __forceinline__ void cp_commit() { asm volatile("cp.async.commit_group;" ::: "memory"); }
template<int N> __device__ __forceinline__ void cp_wait() {
    asm volatile("cp.async.wait_group %0;" :: "n"(N) : "memory");
}

// ---------------- fused tf32 conversion: 7 tensors, one launch ----------------
#define NBIG4 (BB * TT * CC / 4)
#define NWQ4  (CC * CC / 4)
#define NWK4  (NG * HD * CC / 4)

__global__ void __launch_bounds__(256) conv_all(
    const float* __restrict__ q, const float* __restrict__ k, const float* __restrict__ v,
    const float* __restrict__ Wq, const float* __restrict__ Wk,
    const float* __restrict__ Wv, const float* __restrict__ Wp,
    float* __restrict__ qc, float* __restrict__ kc, float* __restrict__ vc,
    float* __restrict__ wq, float* __restrict__ wk, float* __restrict__ wv,
    float* __restrict__ wp)
{
    const float* s; float* d; int n4;
    switch (blockIdx.y) {
        case 0: s = q;  d = qc; n4 = NBIG4; break;
        case 1: s = k;  d = kc; n4 = NBIG4; break;
        case 2: s = v;  d = vc; n4 = NBIG4; break;
        case 3: s = Wq; d = wq; n4 = NWQ4;  break;
        case 4: s = Wp; d = wp; n4 = NWQ4;  break;
        case 5: s = Wk; d = wk; n4 = NWK4;  break;
        default: s = Wv; d = wv; n4 = NWK4; break;
    }
    int i = blockIdx.x * 256 + threadIdx.x;
    if (i >= n4) return;
    float4 t = ((const float4*)s)[i];
    t.x = __uint_as_float(f2tf32(t.x));
    t.y = __uint_as_float(f2tf32(t.y));
    t.z = __uint_as_float(f2tf32(t.z));
    t.w = __uint_as_float(f2tf32(t.w));
    ((float4*)d)[i] = t;
}

// ---------------- V pack+transpose (tf32-rounded fp32, [bg][hd][t]) ----------------
__global__ void __launch_bounds__(256) pack_v(const float* __restrict__ VP,
                                              float* __restrict__ Vt)
{
    __shared__ float tile[64][65];
    const int bg = blockIdx.y;
    const int b  = bg >> 3, g = bg & 7;
    const int t0 = blockIdx.x * 64;
    const int tid = threadIdx.x;

#pragma unroll
    for (int it = 0; it < 4; it++) {
        int idx = tid + it * 256;
        int tl = idx >> 4, c4 = idx & 15;
        float4 v = *(const float4*)(VP + ((size_t)b * TT + t0 + tl) * (NG * HD) + g * 64 + c4 * 4);
        tile[tl][c4 * 4 + 0] = v.x; tile[tl][c4 * 4 + 1] = v.y;
        tile[tl][c4 * 4 + 2] = v.z; tile[tl][c4 * 4 + 3] = v.w;
    }
    __syncthreads();
#pragma unroll
    for (int it = 0; it < 4; it++) {
        int idx = tid + it * 256;       // float4 id over 64x64
        int hd = idx >> 4, t4 = (idx & 15) * 4;
        float4 o;
        o.x = __uint_as_float(f2tf32(tile[t4 + 0][hd]));
        o.y = __uint_as_float(f2tf32(tile[t4 + 1][hd]));
        o.z = __uint_as_float(f2tf32(tile[t4 + 2][hd]));
        o.w = __uint_as_float(f2tf32(tile[t4 + 3][hd]));
        *(float4*)(Vt + ((size_t)bg * 64 + hd) * TT + t0 + t4) = o;
    }
}

// ====== tf32 GEMM: 128x128 CTA, 64x32 warp tile, BK=16, 4-stage single-sync ring, 2 CTAs/SM ======
// GST=24: 64-bit banks 12*grp+tig all distinct -> conflict-free fragment loads.
#define GST 24
#define STGF (256 * GST)                      // 6144 floats = 24576 B / stage
#define NSTG 4
#define GEMM_SMEM_BYTES (NSTG * STGF * 4)     // 98304

__device__ __forceinline__ void gemm_body(
    const float* __restrict__ A, const float* __restrict__ Bm,
    const float* __restrict__ bias, float* __restrict__ Cm,
    int N, int K, int bm, int bn,
    float* __restrict__ Kp)                   // non-null -> tf32-rounded packed-K epilogue
{
    extern __shared__ float smem[];
    const uint32_t smb = smem_u32(smem);

    const int tid  = threadIdx.x;
    const int wid  = tid >> 5;
    const int lane = tid & 31;
    const int grp  = lane >> 2;
    const int tig  = lane & 3;
    const int warp_m = wid >> 2;   // 0..1
    const int warp_n = wid & 3;    // 0..3

    float acc[4][4][4];
#pragma unroll
    for (int i = 0; i < 4; i++)
#pragma unroll
        for (int j = 0; j < 4; j++)
#pragma unroll
            for (int r = 0; r < 4; r++) acc[i][j][r] = 0.f;

    const int NS = K / 16;

    // chunk mapping: c = tid + j*256; row = c>>2 (0-127 A, 128-255 B); c4 = (c&3)*4
#define GISSUE(sl, it) do {                                                             \
        const int _k0 = (it) * 16;                                                      \
        const uint32_t _sb = smb + (uint32_t)(sl) * (STGF * 4);                         \
        _Pragma("unroll")                                                               \
        for (int _j = 0; _j < 4; _j++) {                                                \
            int _c = tid + _j * 256;                                                    \
            int _row = _c >> 2;                                                         \
            int _c4 = (_c & 3) * 4;                                                     \
            const float* _src = (_row < 128)                                            \
                ? (A  + (size_t)(bm + _row) * K + _k0 + _c4)                            \
                : (Bm + (size_t)(bn + _row - 128) * K + _k0 + _c4);                     \
            cp16(_sb + (uint32_t)(_row * GST + _c4) * 4, _src);                         \
        }                                                                               \
    } while (0)

    GISSUE(0, 0); cp_commit();
    GISSUE(1, 1); cp_commit();
    GISSUE(2, 2); cp_commit();

    for (int it = 0; it < NS; it++) {
        cp_wait<2>();
        __syncthreads();                       // single sync per stage
        const int nxt = it + 3;
        if (nxt < NS) { GISSUE(nxt & (NSTG - 1), nxt); }  // slot consumed at it-1, safe
        cp_commit();

        const float* Sb  = smem + (it & (NSTG - 1)) * STGF;
        const float* Bsb = Sb + 128 * GST;
#pragma unroll
        for (int kk = 0; kk < 16; kk += 8) {
            uint2 bfr[4];
#pragma unroll
            for (int na = 0; na < 4; na++)
                bfr[na] = *(const uint2*)(Bsb + (warp_n * 32 + na * 8 + grp) * GST + kk + 2 * tig);
#pragma unroll
            for (int ma = 0; ma < 4; ma++) {
                uint2 av0 = *(const uint2*)(Sb + (warp_m * 64 + ma * 16 + grp) * GST + kk + 2 * tig);
                uint2 av1 = *(const uint2*)(Sb + (warp_m * 64 + ma * 16 + 8 + grp) * GST + kk + 2 * tig);
#pragma unroll
                for (int na = 0; na < 4; na++) {
                    mma_tf32(acc[ma][na][0], acc[ma][na][1], acc[ma][na][2], acc[ma][na][3],
                             av0.x, av1.x, av0.y, av1.y, bfr[na].x, bfr[na].y);
                }
            }
        }
    }
#undef GISSUE

    if (Kp) {
        // packed-K epilogue: tf32-rounded fp32, layout [bg][t][hd]
#pragma unroll
        for (int na = 0; na < 4; na++) {
            const int col = bn + warp_n * 32 + na * 8 + 2 * tig;   // 0..511
            const int g   = col >> 6;
            const int hd  = col & 63;
#pragma unroll
            for (int ma = 0; ma < 4; ma++) {
                const int row = bm + warp_m * 64 + ma * 16 + grp;
                const int b = row >> 11, t = row & (TT - 1);
                float* o = Kp + ((size_t)(b * NG + g) * TT + t) * HD + hd;
                *(float2*)o = make_float2(__uint_as_float(f2tf32(acc[ma][na][0])),
                                          __uint_as_float(f2tf32(acc[ma][na][1])));
                *(float2*)(o + 8 * HD) = make_float2(__uint_as_float(f2tf32(acc[ma][na][2])),
                                                     __uint_as_float(f2tf32(acc[ma][na][3])));
            }
        }
    } else {
#pragma unroll
        for (int na = 0; na < 4; na++) {
            const int col = bn + warp_n * 32 + na * 8 + 2 * tig;
            float b0 = 0.f, b1 = 0.f;
            if (bias) { b0 = bias[col]; b1 = bias[col + 1]; }
#pragma unroll
            for (int ma = 0; ma < 4; ma++) {
                const int row = bm + warp_m * 64 + ma * 16 + grp;
                float2 v0 = make_float2(acc[ma][na][0] + b0, acc[ma][na][1] + b1);
                float2 v1 = make_float2(acc[ma][na][2] + b0, acc[ma][na][3] + b1);
                *(float2*)(Cm + (size_t)row * N + col) = v0;
                *(float2*)(Cm + (size_t)(row + 8) * N + col) = v1;
            }
        }
    }
}

// fused Q + K + V projections: blockIdx.x 0..15 -> Q proj, 16..19 -> K, 20..23 -> V
__global__ void __launch_bounds__(256, 2) gemm_proj(
    const float* __restrict__ qc, const float* __restrict__ kc, const float* __restrict__ vc,
    const float* __restrict__ wq, const float* __restrict__ wk, const float* __restrict__ wv,
    float* __restrict__ QP, float* __restrict__ Kp, float* __restrict__ VP)
{
    const int bx = blockIdx.x;
    if (bx < 16) {
        gemm_body(qc, wq, nullptr, QP, CC, CC, blockIdx.y * 128, bx * 128, nullptr);
    } else if (bx < 20) {
        gemm_body(kc, wk, nullptr, nullptr, NG * HD, CC, blockIdx.y * 128, (bx - 16) * 128, Kp);
    } else {
        gemm_body(vc, wv, nullptr, VP, NG * HD, CC, blockIdx.y * 128, (bx - 20) * 128, nullptr);
    }
}

__global__ void __launch_bounds__(256, 2) gemm_tc(
    const float* __restrict__ A, const float* __restrict__ Bm,
    const float* __restrict__ bias, float* __restrict__ Cm, int N, int K)
{
    gemm_body(A, Bm, bias, Cm, N, K, blockIdx.y * 128, blockIdx.x * 128, nullptr);
}

// ============== flash attention: all-tf32 MMA (S + PV), cp.async ring (R12, unchanged) ==============
#define KST 72
#define STW 9216
#define ATTN_SMEM_BYTES (2 * STW * 4)   // 73728
#define QSCALE 0.1803365407f            // 0.125 * log2(e)

__global__ void __launch_bounds__(256, 1) attn_mma(
    const float* __restrict__ QP, const float* __restrict__ Kp,
    const float* __restrict__ Vtg, float* __restrict__ O)
{
    extern __shared__ uint32_t sm[];
    const uint32_t smb = smem_u32(sm);

    const int bh = blockIdx.y;
    const int b  = bh >> 5;
    const int h  = bh & 31;
    const int g  = h & 7;
    const int bg = b * NG + g;
    const int q0 = blockIdx.x * 128;

    const float* Qg = QP + ((size_t)b * TT + q0) * CC + h * HD;
    const float* Kg = Kp + (size_t)bg * TT * HD;
    const float* Vg = Vtg + (size_t)bg * 64 * TT;

    const int tid  = threadIdx.x;
    const int wid  = tid >> 5;
    const int lane = tid & 31;
    const int grp  = lane >> 2;
    const int tig  = lane & 3;
    const int m0   = wid * 16;

#define ATTN_ISSUE(s, kv) do {                                                            \
        _Pragma("unroll")                                                                 \
        for (int _it = 0; _it < 4; _it++) {                                               \
            int _ch = tid + _it * 256;                                                    \
            int _r = _ch >> 4, _c4 = (_ch & 15) * 4;                                      \
            cp16(smb + (uint32_t)((s) * STW + _r * KST + _c4) * 4,                        \
                 Kg + (size_t)((kv) + _r) * HD + _c4);                                    \
        }                                                                                 \
        _Pragma("unroll")                                                                 \
        for (int _it = 0; _it < 4; _it++) {                                               \
            int _ch = tid + _it * 256;                                                    \
            int _hd = _ch >> 4, _c4 = (_ch & 15) * 4;                                     \
            cp16(smb + (uint32_t)((s) * STW + 4608 + _hd * KST + _c4) * 4,                \
                 Vg + (size_t)_hd * TT + (kv) + _c4);                                     \
        }                                                                                 \
    } while (0)

    ATTN_ISSUE(0, 0);  cp_commit();
    ATTN_ISSUE(1, 64); cp_commit();

    // Q tf32 fragments straight from gmem (k-permuted: slots (tig,tig+4) <- hd (2tig,2tig+1))
    uint32_t qa[8][4];
#pragma unroll
    for (int c = 0; c < 8; c++) {
#pragma unroll
        for (int rr = 0; rr < 2; rr++) {
            const int row = m0 + grp + rr * 8;
            float2 v = *(const float2*)(Qg + (size_t)row * CC + 8 * c + 2 * tig);
            qa[c][rr]     = f2tf32(v.x * QSCALE);
            qa[c][rr + 2] = f2tf32(v.y * QSCALE);
        }
    }

    float oacc[8][4];
#pragma unroll
    for (int i = 0; i < 8; i++)
#pragma unroll
        for (int j = 0; j < 4; j++) oacc[i][j] = 0.f;
    float m_r0 = -INFINITY, m_r1 = -INFINITY, l_r0 = 0.f, l_r1 = 0.f;

    for (int tile = 0; tile < TT / 64; tile++) {
        cp_wait<1>();
        __syncthreads();
        const int s = tile & 1;
        const uint32_t* Ks = sm + s * STW;
        const uint32_t* Vs = Ks + 4608;

        // ---- S = Q @ K^T  (tf32, 8 hd-chunks x 8 key-atoms) ----
        float sacc[8][4];
#pragma unroll
        for (int i = 0; i < 8; i++)
#pragma unroll
            for (int j = 0; j < 4; j++) sacc[i][j] = 0.f;
#pragma unroll
        for (int c = 0; c < 8; c++) {
#pragma unroll
            for (int gg = 0; gg < 8; gg++) {
                uint2 kf = *(const uint2*)(Ks + (8 * gg + grp) * KST + 8 * c + 2 * tig);
                mma_tf32(sacc[gg][0], sacc[gg][1], sacc[gg][2], sacc[gg][3],
                         qa[c][0], qa[c][1], qa[c][2], qa[c][3], kf.x, kf.y);
            }
        }

        // ---- online softmax (base 2) ----
        float rm0 = -INFINITY, rm1 = -INFINITY;
#pragma unroll
        for (int gg = 0; gg < 8; gg++) {
            rm0 = fmaxf(rm0, fmaxf(sacc[gg][0], sacc[gg][1]));
            rm1 = fmaxf(rm1, fmaxf(sacc[gg][2], sacc[gg][3]));
        }
        rm0 = fmaxf(rm0, __shfl_xor_sync(0xffffffffu, rm0, 1));
        rm0 = fmaxf(rm0, __shfl_xor_sync(0xffffffffu, rm0, 2));
        rm1 = fmaxf(rm1, __shfl_xor_sync(0xffffffffu, rm1, 1));
        rm1 = fmaxf(rm1, __shfl_xor_sync(0xffffffffu, rm1, 2));

        float nm0 = fmaxf(m_r0, rm0), nm1 = fmaxf(m_r1, rm1);
        float sc0 = fast_ex2(m_r0 - nm0), sc1 = fast_ex2(m_r1 - nm1);
        m_r0 = nm0; m_r1 = nm1;

        float rs0 = 0.f, rs1 = 0.f;
#pragma unroll
        for (int gg = 0; gg < 8; gg++) {
            sacc[gg][0] = fast_ex2(sacc[gg][0] - nm0);
            sacc[gg][1] = fast_ex2(sacc[gg][1] - nm0);
            sacc[gg][2] = fast_ex2(sacc[gg][2] - nm1);
            sacc[gg][3] = fast_ex2(sacc[gg][3] - nm1);
            rs0 += sacc[gg][0] + sacc[gg][1];
            rs1 += sacc[gg][2] + sacc[gg][3];
        }
        rs0 += __shfl_xor_sync(0xffffffffu, rs0, 1);
        rs0 += __shfl_xor_sync(0xffffffffu, rs0, 2);
        rs1 += __shfl_xor_sync(0xffffffffu, rs1, 1);
        rs1 += __shfl_xor_sync(0xffffffffu, rs1, 2);
        l_r0 = l_r0 * sc0 + rs0;
        l_r1 = l_r1 * sc1 + rs1;
#pragma unroll
        for (int i = 0; i < 8; i++) {
            oacc[i][0] *= sc0; oacc[i][1] *= sc0;
            oacc[i][2] *= sc1; oacc[i][3] *= sc1;
        }

        // ---- O += P @ V  (tf32, permuted k; A-frag = S-accumulator) ----
#pragma unroll
        for (int c = 0; c < 8; c++) {
            const uint32_t pa0 = f2tf32(sacc[c][0]);
            const uint32_t pa1 = f2tf32(sacc[c][2]);
            const uint32_t pa2 = f2tf32(sacc[c][1]);
            const uint32_t pa3 = f2tf32(sacc[c][3]);
#pragma unroll
            for (int hh = 0; hh < 8; hh++) {
                uint2 vf = *(const uint2*)(Vs + (8 * hh + grp) * KST + 8 * c + 2 * tig);
                mma_tf32(oacc[hh][0], oacc[hh][1], oacc[hh][2], oacc[hh][3],
                         pa0, pa1, pa2, pa3, vf.x, vf.y);
            }
        }

        __syncthreads();
        if (tile + 2 < TT / 64) { ATTN_ISSUE(s, (tile + 2) * 64); }
        cp_commit();
    }
#undef ATTN_ISSUE

    const float inv0 = 1.0f / l_r0, inv1 = 1.0f / l_r1;
    float* Og = O + ((size_t)b * TT + q0) * CC + h * HD;
    const int r0 = m0 + grp, r1 = m0 + grp + 8;
#pragma unroll
    for (int hh = 0; hh < 8; hh++) {
        const int col = 8 * hh + 2 * tig;
        float2 v0 = make_float2(__uint_as_float(f2tf32(oacc[hh][0] * inv0)),
                                __uint_as_float(f2tf32(oacc[hh][1] * inv0)));
        float2 v1 = make_float2(__uint_as_float(f2tf32(oacc[hh][2] * inv1)),
                                __uint_as_float(f2tf32(oacc[hh][3] * inv1)));
        *(float2*)(Og + (size_t)r0 * CC + col) = v0;
        *(float2*)(Og + (size_t)r1 * CC + col) = v1;
    }
}

// ---------------- launch ----------------
extern "C" void kernel_launch(void* const* d_in, const int* in_sizes, int n_in,
                              void* d_out, int out_size)
{
    const float* q  = (const float*)d_in[0];
    const float* k  = (const float*)d_in[1];
    const float* v  = (const float*)d_in[2];
    const float* Wq = (const float*)d_in[3];
    const float* Wk = (const float*)d_in[4];
    const float* Wv = (const float*)d_in[5];
    const float* Wp = (const float*)d_in[6];
    const float* bp = (const float*)d_in[7];
    float* out = (float*)d_out;

    float *pQP, *pVP, *pO, *pqc, *pkc, *pvc, *pwq, *pwk, *pwv, *pwp, *pKp, *pVt;
    cudaGetSymbolAddress((void**)&pQP, g_QP);
    cudaGetSymbolAddress((void**)&pVP, g_VP);
    cudaGetSymbolAddress((void**)&pO,  g_O);
    cudaGetSymbolAddress((void**)&pqc, g_qc);
    cudaGetSymbolAddress((void**)&pkc, g_kc);
    cudaGetSymbolAddress((void**)&pvc, g_vc);
    cudaGetSymbolAddress((void**)&pwq, g_wq);
    cudaGetSymbolAddress((void**)&pwk, g_wk);
    cudaGetSymbolAddress((void**)&pwv, g_wv);
    cudaGetSymbolAddress((void**)&pwp, g_wp);
    cudaGetSymbolAddress((void**)&pKp, g_Kp);
    cudaGetSymbolAddress((void**)&pVt, g_Vt);

    cudaFuncSetAttribute(gemm_tc,   cudaFuncAttributeMaxDynamicSharedMemorySize, GEMM_SMEM_BYTES);
    cudaFuncSetAttribute(gemm_proj, cudaFuncAttributeMaxDynamicSharedMemorySize, GEMM_SMEM_BYTES);
    cudaFuncSetAttribute(attn_mma,  cudaFuncAttributeMaxDynamicSharedMemorySize, ATTN_SMEM_BYTES);

    const int M = BB * TT;  // 4096

    conv_all<<<dim3(NBIG4 / 256, 7), 256>>>(q, k, v, Wq, Wk, Wv, Wp,
                                            pqc, pkc, pvc, pwq, pwk, pwv, pwp);

    // fused Q/K/V projections (768 CTAs)
    gemm_proj<<<dim3(24, M / 128), 256, GEMM_SMEM_BYTES>>>(
        pqc, pkc, pvc, pwq, pwk, pwv, pQP, pKp, pVP);
    pack_v<<<dim3(TT / 64, BB * NG), 256>>>(pVP, pVt);

    attn_mma<<<dim3(TT / 128, BB * NH), 256, ATTN_SMEM_BYTES>>>(pQP, pKp, pVt, pO);

    gemm_tc<<<dim3(CC / 128, M / 128), 256, GEMM_SMEM_BYTES>>>(pO, pwp, bp, out, CC, CC);
}

// round 15
// speedup vs baseline: 1.2493x; 1.1414x over previous
#include <cuda_runtime.h>
#include <cuda_bf16.h>
#include <cstdint>
#include <math.h>

#define BB 2
#define TT 2048
#define CC 2048
#define NH 32
#define NG 8
#define HD 64

// ---------------- scratch (no allocations allowed) ----------------
__device__ float g_QP[BB * TT * CC];
__device__ float g_VP[BB * TT * NG * HD];
__device__ float g_qc[BB * TT * CC];
__device__ float g_kc[BB * TT * CC];
__device__ float g_vc[BB * TT * CC];
__device__ float g_wq[CC * CC];
__device__ float g_wk[NG * HD * CC];
__device__ float g_wv[NG * HD * CC];
__device__ float g_wp[CC * CC];
__device__ float g_Kp[BB * NG * TT * HD];    // tf32-rounded fp32 K, [bg][t][hd]
__device__ float g_Vt[BB * NG * HD * TT];    // tf32-rounded fp32 V transposed, [bg][hd][t]
__device__ float g_O[BB * TT * CC];

// ---------------- helpers ----------------
__device__ __forceinline__ uint32_t f2tf32(float x) {
    uint32_t r;
    asm("cvt.rna.tf32.f32 %0, %1;" : "=r"(r) : "f"(x));
    return r;
}
__device__ __forceinline__ float fast_ex2(float x) {
    float r;
    asm("ex2.approx.f32 %0, %1;" : "=f"(r) : "f"(x));
    return r;
}
__device__ __forceinline__ void mma_tf32(float& d0, float& d1, float& d2, float& d3,
                                         uint32_t a0, uint32_t a1, uint32_t a2, uint32_t a3,
                                         uint32_t b0, uint32_t b1)
{
    asm volatile(
        "mma.sync.aligned.m16n8k8.row.col.f32.tf32.tf32.f32 "
        "{%0,%1,%2,%3}, {%4,%5,%6,%7}, {%8,%9}, {%0,%1,%2,%3};"
        : "+f"(d0), "+f"(d1), "+f"(d2), "+f"(d3)
        : "r"(a0), "r"(a1), "r"(a2), "r"(a3), "r"(b0), "r"(b1));
}
__device__ __forceinline__ uint32_t smem_u32(const void* p) {
    uint32_t a;
    asm("{ .reg .u64 t; cvta.to.shared.u64 t, %1; cvt.u32.u64 %0, t; }" : "=r"(a) : "l"(p));
    return a;
}
__device__ __forceinline__ void cp16(uint32_t dst, const void* src) {
    asm volatile("cp.async.ca.shared.global [%0], [%1], 16;" :: "r"(dst), "l"(src));
}
__device__ __forceinline__ void cp_commit() { asm volatile("cp.async.commit_group;" ::: "memory"); }
template<int N> __device__ __forceinline__ void cp_wait() {
    asm volatile("cp.async.wait_group %0;" :: "n"(N) : "memory");
}

// ---------------- fused tf32 conversion: 7 tensors, one launch ----------------
#define NBIG4 (BB * TT * CC / 4)
#define NWQ4  (CC * CC / 4)
#define NWK4  (NG * HD * CC / 4)

__global__ void __launch_bounds__(256) conv_all(
    const float* __restrict__ q, const float* __restrict__ k, const float* __restrict__ v,
    const float* __restrict__ Wq, const float* __restrict__ Wk,
    const float* __restrict__ Wv, const float* __restrict__ Wp,
    float* __restrict__ qc, float* __restrict__ kc, float* __restrict__ vc,
    float* __restrict__ wq, float* __restrict__ wk, float* __restrict__ wv,
    float* __restrict__ wp)
{
    const float* s; float* d; int n4;
    switch (blockIdx.y) {
        case 0: s = q;  d = qc; n4 = NBIG4; break;
        case 1: s = k;  d = kc; n4 = NBIG4; break;
        case 2: s = v;  d = vc; n4 = NBIG4; break;
        case 3: s = Wq; d = wq; n4 = NWQ4;  break;
        case 4: s = Wp; d = wp; n4 = NWQ4;  break;
        case 5: s = Wk; d = wk; n4 = NWK4;  break;
        default: s = Wv; d = wv; n4 = NWK4; break;
    }
    int i = blockIdx.x * 256 + threadIdx.x;
    if (i >= n4) return;
    float4 t = ((const float4*)s)[i];
    t.x = __uint_as_float(f2tf32(t.x));
    t.y = __uint_as_float(f2tf32(t.y));
    t.z = __uint_as_float(f2tf32(t.z));
    t.w = __uint_as_float(f2tf32(t.w));
    ((float4*)d)[i] = t;
}

// ---------------- V pack+transpose (tf32-rounded fp32, [bg][hd][t]) ----------------
__global__ void __launch_bounds__(256) pack_v(const float* __restrict__ VP,
                                              float* __restrict__ Vt)
{
    __shared__ float tile[64][65];
    const int bg = blockIdx.y;
    const int b  = bg >> 3, g = bg & 7;
    const int t0 = blockIdx.x * 64;
    const int tid = threadIdx.x;

#pragma unroll
    for (int it = 0; it < 4; it++) {
        int idx = tid + it * 256;
        int tl = idx >> 4, c4 = idx & 15;
        float4 v = *(const float4*)(VP + ((size_t)b * TT + t0 + tl) * (NG * HD) + g * 64 + c4 * 4);
        tile[tl][c4 * 4 + 0] = v.x; tile[tl][c4 * 4 + 1] = v.y;
        tile[tl][c4 * 4 + 2] = v.z; tile[tl][c4 * 4 + 3] = v.w;
    }
    __syncthreads();
#pragma unroll
    for (int it = 0; it < 4; it++) {
        int idx = tid + it * 256;       // float4 id over 64x64
        int hd = idx >> 4, t4 = (idx & 15) * 4;
        float4 o;
        o.x = __uint_as_float(f2tf32(tile[t4 + 0][hd]));
        o.y = __uint_as_float(f2tf32(tile[t4 + 1][hd]));
        o.z = __uint_as_float(f2tf32(tile[t4 + 2][hd]));
        o.w = __uint_as_float(f2tf32(tile[t4 + 3][hd]));
        *(float4*)(Vt + ((size_t)bg * 64 + hd) * TT + t0 + t4) = o;
    }
}

// ============== tf32 GEMM: 128x128 CTA, 64x32 warp tile, BK=32, 2-stage, 2 CTAs/SM (R12) ==============
#define GST 40
#define STGF (256 * GST)                      // 10240 floats = 40960 B / stage
#define GEMM_SMEM_BYTES (2 * STGF * 4)        // 81920

__device__ __forceinline__ void gemm_body(
    const float* __restrict__ A, const float* __restrict__ Bm,
    const float* __restrict__ bias, float* __restrict__ Cm,
    int N, int K, int bm, int bn,
    float* __restrict__ Kp)                   // non-null -> tf32-rounded packed-K epilogue
{
    extern __shared__ float smem[];
    const uint32_t smb = smem_u32(smem);

    const int tid  = threadIdx.x;
    const int wid  = tid >> 5;
    const int lane = tid & 31;
    const int grp  = lane >> 2;
    const int tig  = lane & 3;
    const int warp_m = wid >> 2;   // 0..1
    const int warp_n = wid & 3;    // 0..3

    float acc[4][4][4];
#pragma unroll
    for (int i = 0; i < 4; i++)
#pragma unroll
        for (int j = 0; j < 4; j++)
#pragma unroll
            for (int r = 0; r < 4; r++) acc[i][j][r] = 0.f;

    const int NS = K / 32;

#define GISSUE(sl, it) do {                                                             \
        const int _k0 = (it) * 32;                                                      \
        const uint32_t _sb = smb + (uint32_t)(sl) * (STGF * 4);                         \
        _Pragma("unroll")                                                               \
        for (int _j = 0; _j < 4; _j++) {                                                \
            int _sl2 = tid + _j * 256;                                                  \
            int _r = _sl2 >> 3, _c4 = (_sl2 & 7) * 4;                                   \
            cp16(_sb + (uint32_t)(_r * GST + _c4) * 4,                                  \
                 A + (size_t)(bm + _r) * K + _k0 + _c4);                                \
            cp16(_sb + (uint32_t)((128 + _r) * GST + _c4) * 4,                          \
                 Bm + (size_t)(bn + _r) * K + _k0 + _c4);                               \
        }                                                                               \
    } while (0)

    GISSUE(0, 0); cp_commit();
    GISSUE(1, 1); cp_commit();

    for (int it = 0; it < NS; it++) {
        cp_wait<1>();
        __syncthreads();

        const int s = it & 1;
        const float* Sb  = smem + s * STGF;
        const float* Bsb = Sb + 128 * GST;
#pragma unroll
        for (int kk = 0; kk < 32; kk += 8) {
            uint2 bfr[4];
#pragma unroll
            for (int na = 0; na < 4; na++)
                bfr[na] = *(const uint2*)(Bsb + (warp_n * 32 + na * 8 + grp) * GST + kk + 2 * tig);
#pragma unroll
            for (int ma = 0; ma < 4; ma++) {
                uint2 av0 = *(const uint2*)(Sb + (warp_m * 64 + ma * 16 + grp) * GST + kk + 2 * tig);
                uint2 av1 = *(const uint2*)(Sb + (warp_m * 64 + ma * 16 + 8 + grp) * GST + kk + 2 * tig);
#pragma unroll
                for (int na = 0; na < 4; na++) {
                    mma_tf32(acc[ma][na][0], acc[ma][na][1], acc[ma][na][2], acc[ma][na][3],
                             av0.x, av1.x, av0.y, av1.y, bfr[na].x, bfr[na].y);
                }
            }
        }

        __syncthreads();                       // stage s fully consumed
        if (it + 2 < NS) { GISSUE(s, it + 2); }
        cp_commit();
    }
#undef GISSUE

    if (Kp) {
        // packed-K epilogue: tf32-rounded fp32, layout [bg][t][hd]
#pragma unroll
        for (int na = 0; na < 4; na++) {
            const int col = bn + warp_n * 32 + na * 8 + 2 * tig;   // 0..511
            const int g   = col >> 6;
            const int hd  = col & 63;
#pragma unroll
            for (int ma = 0; ma < 4; ma++) {
                const int row = bm + warp_m * 64 + ma * 16 + grp;
                const int b = row >> 11, t = row & (TT - 1);
                float* o = Kp + ((size_t)(b * NG + g) * TT + t) * HD + hd;
                *(float2*)o = make_float2(__uint_as_float(f2tf32(acc[ma][na][0])),
                                          __uint_as_float(f2tf32(acc[ma][na][1])));
                *(float2*)(o + 8 * HD) = make_float2(__uint_as_float(f2tf32(acc[ma][na][2])),
                                                     __uint_as_float(f2tf32(acc[ma][na][3])));
            }
        }
    } else {
#pragma unroll
        for (int na = 0; na < 4; na++) {
            const int col = bn + warp_n * 32 + na * 8 + 2 * tig;
            float b0 = 0.f, b1 = 0.f;
            if (bias) { b0 = bias[col]; b1 = bias[col + 1]; }
#pragma unroll
            for (int ma = 0; ma < 4; ma++) {
                const int row = bm + warp_m * 64 + ma * 16 + grp;
                float2 v0 = make_float2(acc[ma][na][0] + b0, acc[ma][na][1] + b1);
                float2 v1 = make_float2(acc[ma][na][2] + b0, acc[ma][na][3] + b1);
                *(float2*)(Cm + (size_t)row * N + col) = v0;
                *(float2*)(Cm + (size_t)(row + 8) * N + col) = v1;
            }
        }
    }
}

__global__ void __launch_bounds__(256, 2) gemm_tc(
    const float* __restrict__ A, const float* __restrict__ Bm,
    const float* __restrict__ bias, float* __restrict__ Cm, int N, int K)
{
    gemm_body(A, Bm, bias, Cm, N, K, blockIdx.y * 128, blockIdx.x * 128, nullptr);
}

__global__ void __launch_bounds__(256, 2) gemm_kv(
    const float* __restrict__ kc, const float* __restrict__ vc,
    const float* __restrict__ wk, const float* __restrict__ wv,
    float* __restrict__ Kp, float* __restrict__ VP)
{
    const bool isV = blockIdx.x >= 4;
    if (isV)
        gemm_body(vc, wv, nullptr, VP, NG * HD, CC, blockIdx.y * 128, (blockIdx.x & 3) * 128,
                  nullptr);
    else
        gemm_body(kc, wk, nullptr, nullptr, NG * HD, CC, blockIdx.y * 128, (blockIdx.x & 3) * 128,
                  Kp);
}

// ============== flash attention: all-tf32 MMA (S + PV), cp.async ring, 2 CTAs/SM ==============
// stage layout (words): K fp32 [64 x 72] at 0, Vt fp32 [64 hd x 72] at 4608
#define KST 72
#define STW 9216
#define ATTN_SMEM_BYTES (2 * STW * 4)   // 73728
#define QSCALE 0.1803365407f            // 0.125 * log2(e)

__global__ void __launch_bounds__(256, 2) attn_mma(
    const float* __restrict__ QP, const float* __restrict__ Kp,
    const float* __restrict__ Vtg, float* __restrict__ O)
{
    extern __shared__ uint32_t sm[];
    const uint32_t smb = smem_u32(sm);

    const int bh = blockIdx.y;
    const int b  = bh >> 5;
    const int h  = bh & 31;
    const int g  = h & 7;
    const int bg = b * NG + g;
    const int q0 = blockIdx.x * 128;

    const float* Qg = QP + ((size_t)b * TT + q0) * CC + h * HD;
    const float* Kg = Kp + (size_t)bg * TT * HD;
    const float* Vg = Vtg + (size_t)bg * 64 * TT;

    const int tid  = threadIdx.x;
    const int wid  = tid >> 5;
    const int lane = tid & 31;
    const int grp  = lane >> 2;
    const int tig  = lane & 3;
    const int m0   = wid * 16;

#define ATTN_ISSUE(s, kv) do {                                                            \
        _Pragma("unroll")                                                                 \
        for (int _it = 0; _it < 4; _it++) {                                               \
            int _ch = tid + _it * 256;                                                    \
            int _r = _ch >> 4, _c4 = (_ch & 15) * 4;                                      \
            cp16(smb + (uint32_t)((s) * STW + _r * KST + _c4) * 4,                        \
                 Kg + (size_t)((kv) + _r) * HD + _c4);                                    \
        }                                                                                 \
        _Pragma("unroll")                                                                 \
        for (int _it = 0; _it < 4; _it++) {                                               \
            int _ch = tid + _it * 256;                                                    \
            int _hd = _ch >> 4, _c4 = (_ch & 15) * 4;                                     \
            cp16(smb + (uint32_t)((s) * STW + 4608 + _hd * KST + _c4) * 4,                \
                 Vg + (size_t)_hd * TT + (kv) + _c4);                                     \
        }                                                                                 \
    } while (0)

    ATTN_ISSUE(0, 0);  cp_commit();
    ATTN_ISSUE(1, 64); cp_commit();

    // Q tf32 fragments straight from gmem (k-permuted: slots (tig,tig+4) <- hd (2tig,2tig+1))
    uint32_t qa[8][4];
#pragma unroll
    for (int c = 0; c < 8; c++) {
#pragma unroll
        for (int rr = 0; rr < 2; rr++) {
            const int row = m0 + grp + rr * 8;
            float2 v = *(const float2*)(Qg + (size_t)row * CC + 8 * c + 2 * tig);
            qa[c][rr]     = f2tf32(v.x * QSCALE);
            qa[c][rr + 2] = f2tf32(v.y * QSCALE);
        }
    }

    float oacc[8][4];
#pragma unroll
    for (int i = 0; i < 8; i++)
#pragma unroll
        for (int j = 0; j < 4; j++) oacc[i][j] = 0.f;
    float m_r0 = -INFINITY, m_r1 = -INFINITY, l_r0 = 0.f, l_r1 = 0.f;

    for (int tile = 0; tile < TT / 64; tile++) {
        cp_wait<1>();
        __syncthreads();
        const int s = tile & 1;
        const uint32_t* Ks = sm + s * STW;
        const uint32_t* Vs = Ks + 4608;

        // ---- S = Q @ K^T  (tf32, 8 hd-chunks x 8 key-atoms) ----
        float sacc[8][4];
#pragma unroll
        for (int i = 0; i < 8; i++)
#pragma unroll
            for (int j = 0; j < 4; j++) sacc[i][j] = 0.f;
#pragma unroll
        for (int c = 0; c < 8; c++) {
#pragma unroll
            for (int gg = 0; gg < 8; gg++) {
                uint2 kf = *(const uint2*)(Ks + (8 * gg + grp) * KST + 8 * c + 2 * tig);
                mma_tf32(sacc[gg][0], sacc[gg][1], sacc[gg][2], sacc[gg][3],
                         qa[c][0], qa[c][1], qa[c][2], qa[c][3], kf.x, kf.y);
            }
        }

        // ---- online softmax (base 2) ----
        float rm0 = -INFINITY, rm1 = -INFINITY;
#pragma unroll
        for (int gg = 0; gg < 8; gg++) {
            rm0 = fmaxf(rm0, fmaxf(sacc[gg][0], sacc[gg][1]));
            rm1 = fmaxf(rm1, fmaxf(sacc[gg][2], sacc[gg][3]));
        }
        rm0 = fmaxf(rm0, __shfl_xor_sync(0xffffffffu, rm0, 1));
        rm0 = fmaxf(rm0, __shfl_xor_sync(0xffffffffu, rm0, 2));
        rm1 = fmaxf(rm1, __shfl_xor_sync(0xffffffffu, rm1, 1));
        rm1 = fmaxf(rm1, __shfl_xor_sync(0xffffffffu, rm1, 2));

        float nm0 = fmaxf(m_r0, rm0), nm1 = fmaxf(m_r1, rm1);
        float sc0 = fast_ex2(m_r0 - nm0), sc1 = fast_ex2(m_r1 - nm1);
        m_r0 = nm0; m_r1 = nm1;

        float rs0 = 0.f, rs1 = 0.f;
#pragma unroll
        for (int gg = 0; gg < 8; gg++) {
            sacc[gg][0] = fast_ex2(sacc[gg][0] - nm0);
            sacc[gg][1] = fast_ex2(sacc[gg][1] - nm0);
            sacc[gg][2] = fast_ex2(sacc[gg][2] - nm1);
            sacc[gg][3] = fast_ex2(sacc[gg][3] - nm1);
            rs0 += sacc[gg][0] + sacc[gg][1];
            rs1 += sacc[gg][2] + sacc[gg][3];
        }
        rs0 += __shfl_xor_sync(0xffffffffu, rs0, 1);
        rs0 += __shfl_xor_sync(0xffffffffu, rs0, 2);
        rs1 += __shfl_xor_sync(0xffffffffu, rs1, 1);
        rs1 += __shfl_xor_sync(0xffffffffu, rs1, 2);
        l_r0 = l_r0 * sc0 + rs0;
        l_r1 = l_r1 * sc1 + rs1;
#pragma unroll
        for (int i = 0; i < 8; i++) {
            oacc[i][0] *= sc0; oacc[i][1] *= sc0;
            oacc[i][2] *= sc1; oacc[i][3] *= sc1;
        }

        // ---- O += P @ V  (tf32, permuted k; A-frag = S-accumulator) ----
#pragma unroll
        for (int c = 0; c < 8; c++) {
            const uint32_t pa0 = f2tf32(sacc[c][0]);
            const uint32_t pa1 = f2tf32(sacc[c][2]);
            const uint32_t pa2 = f2tf32(sacc[c][1]);
            const uint32_t pa3 = f2tf32(sacc[c][3]);
#pragma unroll
            for (int hh = 0; hh < 8; hh++) {
                uint2 vf = *(const uint2*)(Vs + (8 * hh + grp) * KST + 8 * c + 2 * tig);
                mma_tf32(oacc[hh][0], oacc[hh][1], oacc[hh][2], oacc[hh][3],
                         pa0, pa1, pa2, pa3, vf.x, vf.y);
            }
        }

        __syncthreads();
        if (tile + 2 < TT / 64) { ATTN_ISSUE(s, (tile + 2) * 64); }
        cp_commit();
    }
#undef ATTN_ISSUE

    const float inv0 = 1.0f / l_r0, inv1 = 1.0f / l_r1;
    float* Og = O + ((size_t)b * TT + q0) * CC + h * HD;
    const int r0 = m0 + grp, r1 = m0 + grp + 8;
#pragma unroll
    for (int hh = 0; hh < 8; hh++) {
        const int col = 8 * hh + 2 * tig;
        float2 v0 = make_float2(__uint_as_float(f2tf32(oacc[hh][0] * inv0)),
                                __uint_as_float(f2tf32(oacc[hh][1] * inv0)));
        float2 v1 = make_float2(__uint_as_float(f2tf32(oacc[hh][2] * inv1)),
                                __uint_as_float(f2tf32(oacc[hh][3] * inv1)));
        *(float2*)(Og + (size_t)r0 * CC + col) = v0;
        *(float2*)(Og + (size_t)r1 * CC + col) = v1;
    }
}

// ---------------- launch ----------------
extern "C" void kernel_launch(void* const* d_in, const int* in_sizes, int n_in,
                              void* d_out, int out_size)
{
    const float* q  = (const float*)d_in[0];
    const float* k  = (const float*)d_in[1];
    const float* v  = (const float*)d_in[2];
    const float* Wq = (const float*)d_in[3];
    const float* Wk = (const float*)d_in[4];
    const float* Wv = (const float*)d_in[5];
    const float* Wp = (const float*)d_in[6];
    const float* bp = (const float*)d_in[7];
    float* out = (float*)d_out;

    float *pQP, *pVP, *pO, *pqc, *pkc, *pvc, *pwq, *pwk, *pwv, *pwp, *pKp, *pVt;
    cudaGetSymbolAddress((void**)&pQP, g_QP);
    cudaGetSymbolAddress((void**)&pVP, g_VP);
    cudaGetSymbolAddress((void**)&pO,  g_O);
    cudaGetSymbolAddress((void**)&pqc, g_qc);
    cudaGetSymbolAddress((void**)&pkc, g_kc);
    cudaGetSymbolAddress((void**)&pvc, g_vc);
    cudaGetSymbolAddress((void**)&pwq, g_wq);
    cudaGetSymbolAddress((void**)&pwk, g_wk);
    cudaGetSymbolAddress((void**)&pwv, g_wv);
    cudaGetSymbolAddress((void**)&pwp, g_wp);
    cudaGetSymbolAddress((void**)&pKp, g_Kp);
    cudaGetSymbolAddress((void**)&pVt, g_Vt);

    cudaFuncSetAttribute(gemm_tc,  cudaFuncAttributeMaxDynamicSharedMemorySize, GEMM_SMEM_BYTES);
    cudaFuncSetAttribute(gemm_kv,  cudaFuncAttributeMaxDynamicSharedMemorySize, GEMM_SMEM_BYTES);
    cudaFuncSetAttribute(attn_mma, cudaFuncAttributeMaxDynamicSharedMemorySize, ATTN_SMEM_BYTES);

    const int M = BB * TT;  // 4096

    conv_all<<<dim3(NBIG4 / 256, 7), 256>>>(q, k, v, Wq, Wk, Wv, Wp,
                                            pqc, pkc, pvc, pwq, pwk, pwv, pwp);

    gemm_tc<<<dim3(CC / 128, M / 128), 256, GEMM_SMEM_BYTES>>>(pqc, pwq, nullptr, pQP, CC, CC);
    gemm_kv<<<dim3(8, M / 128), 256, GEMM_SMEM_BYTES>>>(pkc, pvc, pwk, pwv, pKp, pVP);
    pack_v<<<dim3(TT / 64, BB * NG), 256>>>(pVP, pVt);

    attn_mma<<<dim3(TT / 128, BB * NH), 256, ATTN_SMEM_BYTES>>>(pQP, pKp, pVt, pO);

    gemm_tc<<<dim3(CC / 128, M / 128), 256, GEMM_SMEM_BYTES>>>(pO, pwp, bp, out, CC, CC);
}

// round 16
// speedup vs baseline: 1.2941x; 1.0359x over previous
#include <cuda_runtime.h>
#include <cuda_bf16.h>
#include <cstdint>
#include <math.h>

#define BB 2
#define TT 2048
#define CC 2048
#define NH 32
#define NG 8
#define HD 64

// ---------------- scratch (no allocations allowed) ----------------
__device__ float g_QP[BB * TT * CC];
__device__ float g_VP[BB * TT * NG * HD];
__device__ float g_qc[BB * TT * CC];
__device__ float g_kc[BB * TT * CC];
__device__ float g_vc[BB * TT * CC];
__device__ float g_wq[CC * CC];
__device__ float g_wk[NG * HD * CC];
__device__ float g_wv[NG * HD * CC];
__device__ float g_wp[CC * CC];
__device__ float g_Kp[BB * NG * TT * HD];    // tf32-rounded fp32 K, [bg][t][hd]
__device__ float g_Vt[BB * NG * HD * TT];    // tf32-rounded fp32 V transposed, [bg][hd][t]
__device__ float g_O[BB * TT * CC];

// ---------------- helpers ----------------
__device__ __forceinline__ uint32_t f2tf32(float x) {
    uint32_t r;
    asm("cvt.rna.tf32.f32 %0, %1;" : "=r"(r) : "f"(x));
    return r;
}
__device__ __forceinline__ float fast_ex2(float x) {
    float r;
    asm("ex2.approx.f32 %0, %1;" : "=f"(r) : "f"(x));
    return r;
}
__device__ __forceinline__ void mma_tf32(float& d0, float& d1, float& d2, float& d3,
                                         uint32_t a0, uint32_t a1, uint32_t a2, uint32_t a3,
                                         uint32_t b0, uint32_t b1)
{
    asm volatile(
        "mma.sync.aligned.m16n8k8.row.col.f32.tf32.tf32.f32 "
        "{%0,%1,%2,%3}, {%4,%5,%6,%7}, {%8,%9}, {%0,%1,%2,%3};"
        : "+f"(d0), "+f"(d1), "+f"(d2), "+f"(d3)
        : "r"(a0), "r"(a1), "r"(a2), "r"(a3), "r"(b0), "r"(b1));
}
__device__ __forceinline__ uint32_t smem_u32(const void* p) {
    uint32_t a;
    asm("{ .reg .u64 t; cvta.to.shared.u64 t, %1; cvt.u32.u64 %0, t; }" : "=r"(a) : "l"(p));
    return a;
}
__device__ __forceinline__ void cp16(uint32_t dst, const void* src) {
    asm volatile("cp.async.ca.shared.global [%0], [%1], 16;" :: "r"(dst), "l"(src));
}
__device__ __forceinline__ void cp_commit() { asm volatile("cp.async.commit_group;" ::: "memory"); }
template<int N> __device__ __forceinline__ void cp_wait() {
    asm volatile("cp.async.wait_group %0;" :: "n"(N) : "memory");
}

// ---------------- fused tf32 conversion: 7 tensors, one launch ----------------
#define NBIG4 (BB * TT * CC / 4)
#define NWQ4  (CC * CC / 4)
#define NWK4  (NG * HD * CC / 4)

__global__ void __launch_bounds__(256) conv_all(
    const float* __restrict__ q, const float* __restrict__ k, const float* __restrict__ v,
    const float* __restrict__ Wq, const float* __restrict__ Wk,
    const float* __restrict__ Wv, const float* __restrict__ Wp,
    float* __restrict__ qc, float* __restrict__ kc, float* __restrict__ vc,
    float* __restrict__ wq, float* __restrict__ wk, float* __restrict__ wv,
    float* __restrict__ wp)
{
    const float* s; float* d; int n4;
    switch (blockIdx.y) {
        case 0: s = q;  d = qc; n4 = NBIG4; break;
        case 1: s = k;  d = kc; n4 = NBIG4; break;
        case 2: s = v;  d = vc; n4 = NBIG4; break;
        case 3: s = Wq; d = wq; n4 = NWQ4;  break;
        case 4: s = Wp; d = wp; n4 = NWQ4;  break;
        case 5: s = Wk; d = wk; n4 = NWK4;  break;
        default: s = Wv; d = wv; n4 = NWK4; break;
    }
    int i = blockIdx.x * 256 + threadIdx.x;
    if (i >= n4) return;
    float4 t = ((const float4*)s)[i];
    t.x = __uint_as_float(f2tf32(t.x));
    t.y = __uint_as_float(f2tf32(t.y));
    t.z = __uint_as_float(f2tf32(t.z));
    t.w = __uint_as_float(f2tf32(t.w));
    ((float4*)d)[i] = t;
}

// ---------------- V pack+transpose (tf32-rounded fp32, [bg][hd][t]) ----------------
__global__ void __launch_bounds__(256) pack_v(const float* __restrict__ VP,
                                              float* __restrict__ Vt)
{
    __shared__ float tile[64][65];
    const int bg = blockIdx.y;
    const int b  = bg >> 3, g = bg & 7;
    const int t0 = blockIdx.x * 64;
    const int tid = threadIdx.x;

#pragma unroll
    for (int it = 0; it < 4; it++) {
        int idx = tid + it * 256;
        int tl = idx >> 4, c4 = idx & 15;
        float4 v = *(const float4*)(VP + ((size_t)b * TT + t0 + tl) * (NG * HD) + g * 64 + c4 * 4);
        tile[tl][c4 * 4 + 0] = v.x; tile[tl][c4 * 4 + 1] = v.y;
        tile[tl][c4 * 4 + 2] = v.z; tile[tl][c4 * 4 + 3] = v.w;
    }
    __syncthreads();
#pragma unroll
    for (int it = 0; it < 4; it++) {
        int idx = tid + it * 256;       // float4 id over 64x64
        int hd = idx >> 4, t4 = (idx & 15) * 4;
        float4 o;
        o.x = __uint_as_float(f2tf32(tile[t4 + 0][hd]));
        o.y = __uint_as_float(f2tf32(tile[t4 + 1][hd]));
        o.z = __uint_as_float(f2tf32(tile[t4 + 2][hd]));
        o.w = __uint_as_float(f2tf32(tile[t4 + 3][hd]));
        *(float4*)(Vt + ((size_t)bg * 64 + hd) * TT + t0 + t4) = o;
    }
}

// ====== tf32 GEMM: 128x128 CTA, 128 threads, 4 warps (2x2), warp tile 64x64, BK=32 ======
// GST=48 (== 16 mod 32): LDS.128 k-pair loads conflict-free; 2 MMAs per uint4 (k-permuted).
#define GST 48
#define STGF (256 * GST)                      // 12288 floats = 49152 B / stage
#define GEMM_SMEM_BYTES (2 * STGF * 4)        // 98304

__device__ __forceinline__ void gemm_body(
    const float* __restrict__ A, const float* __restrict__ Bm,
    const float* __restrict__ bias, float* __restrict__ Cm,
    int N, int K, int bm, int bn,
    float* __restrict__ Kp)                   // non-null -> tf32-rounded packed-K epilogue
{
    extern __shared__ float smem[];
    const uint32_t smb = smem_u32(smem);

    const int tid  = threadIdx.x;
    const int wid  = tid >> 5;
    const int lane = tid & 31;
    const int grp  = lane >> 2;
    const int tig  = lane & 3;
    const int warp_m = wid >> 1;   // 0..1
    const int warp_n = wid & 1;    // 0..1

    float acc[4][8][4];
#pragma unroll
    for (int i = 0; i < 4; i++)
#pragma unroll
        for (int j = 0; j < 8; j++)
#pragma unroll
            for (int r = 0; r < 4; r++) acc[i][j][r] = 0.f;

    const int NS = K / 32;

    // 2048 float4 per stage, 128 threads -> 16 cp16/thread
#define GISSUE(sl, it) do {                                                             \
        const int _k0 = (it) * 32;                                                      \
        const uint32_t _sb = smb + (uint32_t)(sl) * (STGF * 4);                         \
        _Pragma("unroll")                                                               \
        for (int _j = 0; _j < 8; _j++) {                                                \
            int _c = tid + _j * 128;                                                    \
            int _r = _c >> 3, _c4 = (_c & 7) * 4;                                       \
            cp16(_sb + (uint32_t)(_r * GST + _c4) * 4,                                  \
                 A + (size_t)(bm + _r) * K + _k0 + _c4);                                \
            cp16(_sb + (uint32_t)((128 + _r) * GST + _c4) * 4,                          \
                 Bm + (size_t)(bn + _r) * K + _k0 + _c4);                               \
        }                                                                               \
    } while (0)

    GISSUE(0, 0); cp_commit();
    GISSUE(1, 1); cp_commit();

    for (int it = 0; it < NS; it++) {
        cp_wait<1>();
        __syncthreads();

        const int s = it & 1;
        const float* Sb  = smem + s * STGF;
        const float* Bsb = Sb + 128 * GST;
        // k-pair permuted: uint4 at col kkp+4*tig covers 2 MMA chunks
        //   chunk0: hw slots (tig,tig+4) <- k (kkp+4tig, kkp+4tig+1)
        //   chunk1: hw slots (tig,tig+4) <- k (kkp+4tig+2, kkp+4tig+3)
#pragma unroll
        for (int kkp = 0; kkp < 32; kkp += 16) {
            uint4 bf[8];
#pragma unroll
            for (int na = 0; na < 8; na++)
                bf[na] = *(const uint4*)(Bsb + (warp_n * 64 + na * 8 + grp) * GST + kkp + 4 * tig);
#pragma unroll
            for (int ma = 0; ma < 4; ma++) {
                uint4 a0 = *(const uint4*)(Sb + (warp_m * 64 + ma * 16 + grp) * GST + kkp + 4 * tig);
                uint4 a1 = *(const uint4*)(Sb + (warp_m * 64 + ma * 16 + 8 + grp) * GST + kkp + 4 * tig);
#pragma unroll
                for (int na = 0; na < 8; na++) {
                    mma_tf32(acc[ma][na][0], acc[ma][na][1], acc[ma][na][2], acc[ma][na][3],
                             a0.x, a1.x, a0.y, a1.y, bf[na].x, bf[na].y);
                    mma_tf32(acc[ma][na][0], acc[ma][na][1], acc[ma][na][2], acc[ma][na][3],
                             a0.z, a1.z, a0.w, a1.w, bf[na].z, bf[na].w);
                }
            }
        }

        __syncthreads();                       // stage s fully consumed
        if (it + 2 < NS) { GISSUE(s, it + 2); }
        cp_commit();
    }
#undef GISSUE

    if (Kp) {
        // packed-K epilogue: tf32-rounded fp32, layout [bg][t][hd]
#pragma unroll
        for (int na = 0; na < 8; na++) {
            const int col = bn + warp_n * 64 + na * 8 + 2 * tig;   // 0..511
            const int g   = col >> 6;
            const int hd  = col & 63;
#pragma unroll
            for (int ma = 0; ma < 4; ma++) {
                const int row = bm + warp_m * 64 + ma * 16 + grp;
                const int b = row >> 11, t = row & (TT - 1);
                float* o = Kp + ((size_t)(b * NG + g) * TT + t) * HD + hd;
                *(float2*)o = make_float2(__uint_as_float(f2tf32(acc[ma][na][0])),
                                          __uint_as_float(f2tf32(acc[ma][na][1])));
                *(float2*)(o + 8 * HD) = make_float2(__uint_as_float(f2tf32(acc[ma][na][2])),
                                                     __uint_as_float(f2tf32(acc[ma][na][3])));
            }
        }
    } else {
#pragma unroll
        for (int na = 0; na < 8; na++) {
            const int col = bn + warp_n * 64 + na * 8 + 2 * tig;
            float b0 = 0.f, b1 = 0.f;
            if (bias) { b0 = bias[col]; b1 = bias[col + 1]; }
#pragma unroll
            for (int ma = 0; ma < 4; ma++) {
                const int row = bm + warp_m * 64 + ma * 16 + grp;
                float2 v0 = make_float2(acc[ma][na][0] + b0, acc[ma][na][1] + b1);
                float2 v1 = make_float2(acc[ma][na][2] + b0, acc[ma][na][3] + b1);
                *(float2*)(Cm + (size_t)row * N + col) = v0;
                *(float2*)(Cm + (size_t)(row + 8) * N + col) = v1;
            }
        }
    }
}

// fused Q + K + V projections: blockIdx.x 0..15 -> Q, 16..19 -> K(packed), 20..23 -> V
__global__ void __launch_bounds__(128, 2) gemm_proj(
    const float* __restrict__ qc, const float* __restrict__ kc, const float* __restrict__ vc,
    const float* __restrict__ wq, const float* __restrict__ wk, const float* __restrict__ wv,
    float* __restrict__ QP, float* __restrict__ Kp, float* __restrict__ VP)
{
    const int bx = blockIdx.x;
    if (bx < 16) {
        gemm_body(qc, wq, nullptr, QP, CC, CC, blockIdx.y * 128, bx * 128, nullptr);
    } else if (bx < 20) {
        gemm_body(kc, wk, nullptr, nullptr, NG * HD, CC, blockIdx.y * 128, (bx - 16) * 128, Kp);
    } else {
        gemm_body(vc, wv, nullptr, VP, NG * HD, CC, blockIdx.y * 128, (bx - 20) * 128, nullptr);
    }
}

__global__ void __launch_bounds__(128, 2) gemm_tc(
    const float* __restrict__ A, const float* __restrict__ Bm,
    const float* __restrict__ bias, float* __restrict__ Cm, int N, int K)
{
    gemm_body(A, Bm, bias, Cm, N, K, blockIdx.y * 128, blockIdx.x * 128, nullptr);
}

// ============== flash attention: all-tf32 MMA (S + PV), cp.async ring, 2 CTAs/SM (R15) ==============
#define KST 72
#define STW 9216
#define ATTN_SMEM_BYTES (2 * STW * 4)   // 73728
#define QSCALE 0.1803365407f            // 0.125 * log2(e)

__global__ void __launch_bounds__(256, 2) attn_mma(
    const float* __restrict__ QP, const float* __restrict__ Kp,
    const float* __restrict__ Vtg, float* __restrict__ O)
{
    extern __shared__ uint32_t sm[];
    const uint32_t smb = smem_u32(sm);

    const int bh = blockIdx.y;
    const int b  = bh >> 5;
    const int h  = bh & 31;
    const int g  = h & 7;
    const int bg = b * NG + g;
    const int q0 = blockIdx.x * 128;

    const float* Qg = QP + ((size_t)b * TT + q0) * CC + h * HD;
    const float* Kg = Kp + (size_t)bg * TT * HD;
    const float* Vg = Vtg + (size_t)bg * 64 * TT;

    const int tid  = threadIdx.x;
    const int wid  = tid >> 5;
    const int lane = tid & 31;
    const int grp  = lane >> 2;
    const int tig  = lane & 3;
    const int m0   = wid * 16;

#define ATTN_ISSUE(s, kv) do {                                                            \
        _Pragma("unroll")                                                                 \
        for (int _it = 0; _it < 4; _it++) {                                               \
            int _ch = tid + _it * 256;                                                    \
            int _r = _ch >> 4, _c4 = (_ch & 15) * 4;                                      \
            cp16(smb + (uint32_t)((s) * STW + _r * KST + _c4) * 4,                        \
                 Kg + (size_t)((kv) + _r) * HD + _c4);                                    \
        }                                                                                 \
        _Pragma("unroll")                                                                 \
        for (int _it = 0; _it < 4; _it++) {                                               \
            int _ch = tid + _it * 256;                                                    \
            int _hd = _ch >> 4, _c4 = (_ch & 15) * 4;                                     \
            cp16(smb + (uint32_t)((s) * STW + 4608 + _hd * KST + _c4) * 4,                \
                 Vg + (size_t)_hd * TT + (kv) + _c4);                                     \
        }                                                                                 \
    } while (0)

    ATTN_ISSUE(0, 0);  cp_commit();
    ATTN_ISSUE(1, 64); cp_commit();

    // Q tf32 fragments straight from gmem (k-permuted: slots (tig,tig+4) <- hd (2tig,2tig+1))
    uint32_t qa[8][4];
#pragma unroll
    for (int c = 0; c < 8; c++) {
#pragma unroll
        for (int rr = 0; rr < 2; rr++) {
            const int row = m0 + grp + rr * 8;
            float2 v = *(const float2*)(Qg + (size_t)row * CC + 8 * c + 2 * tig);
            qa[c][rr]     = f2tf32(v.x * QSCALE);
            qa[c][rr + 2] = f2tf32(v.y * QSCALE);
        }
    }

    float oacc[8][4];
#pragma unroll
    for (int i = 0; i < 8; i++)
#pragma unroll
        for (int j = 0; j < 4; j++) oacc[i][j] = 0.f;
    float m_r0 = -INFINITY, m_r1 = -INFINITY, l_r0 = 0.f, l_r1 = 0.f;

    for (int tile = 0; tile < TT / 64; tile++) {
        cp_wait<1>();
        __syncthreads();
        const int s = tile & 1;
        const uint32_t* Ks = sm + s * STW;
        const uint32_t* Vs = Ks + 4608;

        // ---- S = Q @ K^T  (tf32, 8 hd-chunks x 8 key-atoms) ----
        float sacc[8][4];
#pragma unroll
        for (int i = 0; i < 8; i++)
#pragma unroll
            for (int j = 0; j < 4; j++) sacc[i][j] = 0.f;
#pragma unroll
        for (int c = 0; c < 8; c++) {
#pragma unroll
            for (int gg = 0; gg < 8; gg++) {
                uint2 kf = *(const uint2*)(Ks + (8 * gg + grp) * KST + 8 * c + 2 * tig);
                mma_tf32(sacc[gg][0], sacc[gg][1], sacc[gg][2], sacc[gg][3],
                         qa[c][0], qa[c][1], qa[c][2], qa[c][3], kf.x, kf.y);
            }
        }

        // ---- online softmax (base 2) ----
        float rm0 = -INFINITY, rm1 = -INFINITY;
#pragma unroll
        for (int gg = 0; gg < 8; gg++) {
            rm0 = fmaxf(rm0, fmaxf(sacc[gg][0], sacc[gg][1]));
            rm1 = fmaxf(rm1, fmaxf(sacc[gg][2], sacc[gg][3]));
        }
        rm0 = fmaxf(rm0, __shfl_xor_sync(0xffffffffu, rm0, 1));
        rm0 = fmaxf(rm0, __shfl_xor_sync(0xffffffffu, rm0, 2));
        rm1 = fmaxf(rm1, __shfl_xor_sync(0xffffffffu, rm1, 1));
        rm1 = fmaxf(rm1, __shfl_xor_sync(0xffffffffu, rm1, 2));

        float nm0 = fmaxf(m_r0, rm0), nm1 = fmaxf(m_r1, rm1);
        float sc0 = fast_ex2(m_r0 - nm0), sc1 = fast_ex2(m_r1 - nm1);
        m_r0 = nm0; m_r1 = nm1;

        float rs0 = 0.f, rs1 = 0.f;
#pragma unroll
        for (int gg = 0; gg < 8; gg++) {
            sacc[gg][0] = fast_ex2(sacc[gg][0] - nm0);
            sacc[gg][1] = fast_ex2(sacc[gg][1] - nm0);
            sacc[gg][2] = fast_ex2(sacc[gg][2] - nm1);
            sacc[gg][3] = fast_ex2(sacc[gg][3] - nm1);
            rs0 += sacc[gg][0] + sacc[gg][1];
            rs1 += sacc[gg][2] + sacc[gg][3];
        }
        rs0 += __shfl_xor_sync(0xffffffffu, rs0, 1);
        rs0 += __shfl_xor_sync(0xffffffffu, rs0, 2);
        rs1 += __shfl_xor_sync(0xffffffffu, rs1, 1);
        rs1 += __shfl_xor_sync(0xffffffffu, rs1, 2);
        l_r0 = l_r0 * sc0 + rs0;
        l_r1 = l_r1 * sc1 + rs1;
#pragma unroll
        for (int i = 0; i < 8; i++) {
            oacc[i][0] *= sc0; oacc[i][1] *= sc0;
            oacc[i][2] *= sc1; oacc[i][3] *= sc1;
        }

        // ---- O += P @ V  (tf32, permuted k; A-frag = S-accumulator) ----
#pragma unroll
        for (int c = 0; c < 8; c++) {
            const uint32_t pa0 = f2tf32(sacc[c][0]);
            const uint32_t pa1 = f2tf32(sacc[c][2]);
            const uint32_t pa2 = f2tf32(sacc[c][1]);
            const uint32_t pa3 = f2tf32(sacc[c][3]);
#pragma unroll
            for (int hh = 0; hh < 8; hh++) {
                uint2 vf = *(const uint2*)(Vs + (8 * hh + grp) * KST + 8 * c + 2 * tig);
                mma_tf32(oacc[hh][0], oacc[hh][1], oacc[hh][2], oacc[hh][3],
                         pa0, pa1, pa2, pa3, vf.x, vf.y);
            }
        }

        __syncthreads();
        if (tile + 2 < TT / 64) { ATTN_ISSUE(s, (tile + 2) * 64); }
        cp_commit();
    }
#undef ATTN_ISSUE

    const float inv0 = 1.0f / l_r0, inv1 = 1.0f / l_r1;
    float* Og = O + ((size_t)b * TT + q0) * CC + h * HD;
    const int r0 = m0 + grp, r1 = m0 + grp + 8;
#pragma unroll
    for (int hh = 0; hh < 8; hh++) {
        const int col = 8 * hh + 2 * tig;
        float2 v0 = make_float2(__uint_as_float(f2tf32(oacc[hh][0] * inv0)),
                                __uint_as_float(f2tf32(oacc[hh][1] * inv0)));
        float2 v1 = make_float2(__uint_as_float(f2tf32(oacc[hh][2] * inv1)),
                                __uint_as_float(f2tf32(oacc[hh][3] * inv1)));
        *(float2*)(Og + (size_t)r0 * CC + col) = v0;
        *(float2*)(Og + (size_t)r1 * CC + col) = v1;
    }
}

// ---------------- launch ----------------
extern "C" void kernel_launch(void* const* d_in, const int* in_sizes, int n_in,
                              void* d_out, int out_size)
{
    const float* q  = (const float*)d_in[0];
    const float* k  = (const float*)d_in[1];
    const float* v  = (const float*)d_in[2];
    const float* Wq = (const float*)d_in[3];
    const float* Wk = (const float*)d_in[4];
    const float* Wv = (const float*)d_in[5];
    const float* Wp = (const float*)d_in[6];
    const float* bp = (const float*)d_in[7];
    float* out = (float*)d_out;

    float *pQP, *pVP, *pO, *pqc, *pkc, *pvc, *pwq, *pwk, *pwv, *pwp, *pKp, *pVt;
    cudaGetSymbolAddress((void**)&pQP, g_QP);
    cudaGetSymbolAddress((void**)&pVP, g_VP);
    cudaGetSymbolAddress((void**)&pO,  g_O);
    cudaGetSymbolAddress((void**)&pqc, g_qc);
    cudaGetSymbolAddress((void**)&pkc, g_kc);
    cudaGetSymbolAddress((void**)&pvc, g_vc);
    cudaGetSymbolAddress((void**)&pwq, g_wq);
    cudaGetSymbolAddress((void**)&pwk, g_wk);
    cudaGetSymbolAddress((void**)&pwv, g_wv);
    cudaGetSymbolAddress((void**)&pwp, g_wp);
    cudaGetSymbolAddress((void**)&pKp, g_Kp);
    cudaGetSymbolAddress((void**)&pVt, g_Vt);

    cudaFuncSetAttribute(gemm_tc,   cudaFuncAttributeMaxDynamicSharedMemorySize, GEMM_SMEM_BYTES);
    cudaFuncSetAttribute(gemm_proj, cudaFuncAttributeMaxDynamicSharedMemorySize, GEMM_SMEM_BYTES);
    cudaFuncSetAttribute(attn_mma,  cudaFuncAttributeMaxDynamicSharedMemorySize, ATTN_SMEM_BYTES);

    const int M = BB * TT;  // 4096

    conv_all<<<dim3(NBIG4 / 256, 7), 256>>>(q, k, v, Wq, Wk, Wv, Wp,
                                            pqc, pkc, pvc, pwq, pwk, pwv, pwp);

    // fused Q/K/V projections (768 CTAs of 128 threads)
    gemm_proj<<<dim3(24, M / 128), 128, GEMM_SMEM_BYTES>>>(
        pqc, pkc, pvc, pwq, pwk, pwv, pQP, pKp, pVP);
    pack_v<<<dim3(TT / 64, BB * NG), 256>>>(pVP, pVt);

    attn_mma<<<dim3(TT / 128, BB * NH), 256, ATTN_SMEM_BYTES>>>(pQP, pKp, pVt, pO);

    gemm_tc<<<dim3(CC / 128, M / 128), 128, GEMM_SMEM_BYTES>>>(pO, pwp, bp, out, CC, CC);
}